// round 4
// baseline (speedup 1.0000x reference)
#include <cuda_runtime.h>

// ---------------------------------------------------------------------------
// Elman RNN (relu), B=64, T=512, I=64, H=1024, O=64
// out = [ hidden_list (B,T,H) | output_list (B,T,O) | h_last (1,B,H) ]
// ---------------------------------------------------------------------------

#define B_   64
#define T_   512
#define I_   64
#define H_   1024
#define O_   64

#define HID_OFF  0
#define OUT_OFF  (B_ * T_ * H_)              // 33554432
#define HL_OFF   (OUT_OFF + B_ * T_ * O_)    // 35651584

#define NBLK 128        // persistent blocks (1/SM)
#define TB   256

// SMEM layout (floats): 32 super-chunks of 32 floats padded to 34.
// A K-chunk of 16 floats is half a super-chunk: offset (kc>>1)*34 + (kc&1)*16.
#define CH    34
#define HRow  1088      // 32 * 34
#define RST   66        // reduction row: 64 partials + 2 pad

// scratch: h double buffer + per-chain barrier state (8 chains)
__device__ float    g_hbuf[2][B_ * H_];
__device__ unsigned g_cnt[8 * 32];
__device__ unsigned g_gen2[8 * 32];

typedef unsigned long long ull;

__device__ __forceinline__ ull f2fma(ull a, ull b, ull c) {
    ull d;
    asm("fma.rn.f32x2 %0, %1, %2, %3;" : "=l"(d) : "l"(a), "l"(b), "l"(c));
    return d;
}
__device__ __forceinline__ ull f2add(ull a, ull b) {
    ull d;
    asm("add.rn.f32x2 %0, %1, %2;" : "=l"(d) : "l"(a), "l"(b));
    return d;
}
__device__ __forceinline__ float pairsum(ull a) {
    float lo = __uint_as_float((unsigned)(a & 0xffffffffull));
    float hi = __uint_as_float((unsigned)(a >> 32));
    return lo + hi;
}

// ---------------------------------------------------------------------------
// Kernel A: xw[bt][h] = x[bt]·W_ih[h] + b_ih[h] + b_hh[h]  -> hidden region
// ---------------------------------------------------------------------------
__global__ void __launch_bounds__(256) xw_kernel(
    const float* __restrict__ x, const float* __restrict__ Wih,
    const float* __restrict__ bih, const float* __restrict__ bhh,
    float* __restrict__ hid_out)
{
    __shared__ float xs[64 * 65];
    __shared__ float ws[64 * 65];

    const int tid = threadIdx.x;
    const int hb  = blockIdx.x * 64;
    const int btb = blockIdx.y * 64;

    #pragma unroll
    for (int i = tid; i < 64 * 64; i += 256) {
        int r = i >> 6, c = i & 63;
        xs[r * 65 + c] = x[(btb + r) * 64 + c];
        ws[r * 65 + c] = Wih[(hb + r) * 64 + c];
    }
    __syncthreads();

    const int tx = tid & 15, ty = tid >> 4;
    float acc[4][4] = {};

    #pragma unroll 8
    for (int k = 0; k < 64; ++k) {
        float a0 = xs[(ty     ) * 65 + k];
        float a1 = xs[(ty + 16) * 65 + k];
        float a2 = xs[(ty + 32) * 65 + k];
        float a3 = xs[(ty + 48) * 65 + k];
        float b0 = ws[(tx     ) * 65 + k];
        float b1 = ws[(tx + 16) * 65 + k];
        float b2 = ws[(tx + 32) * 65 + k];
        float b3 = ws[(tx + 48) * 65 + k];
        acc[0][0] += a0 * b0; acc[0][1] += a0 * b1; acc[0][2] += a0 * b2; acc[0][3] += a0 * b3;
        acc[1][0] += a1 * b0; acc[1][1] += a1 * b1; acc[1][2] += a1 * b2; acc[1][3] += a1 * b3;
        acc[2][0] += a2 * b0; acc[2][1] += a2 * b1; acc[2][2] += a2 * b2; acc[2][3] += a2 * b3;
        acc[3][0] += a3 * b0; acc[3][1] += a3 * b1; acc[3][2] += a3 * b2; acc[3][3] += a3 * b3;
    }

    #pragma unroll
    for (int j = 0; j < 4; ++j) {
        int h = hb + tx + 16 * j;
        float bb = bih[h] + bhh[h];
        #pragma unroll
        for (int i = 0; i < 4; ++i) {
            int bt = btb + ty + 16 * i;
            hid_out[bt * H_ + h] = acc[i][j] + bb;
        }
    }
}

// ---------------------------------------------------------------------------
// Kernel B: persistent recurrence, TWO interleaved chains per block.
// 8 chains of 8 batches; 32 col-groups of 32 cols; block = (pair, cg):
//   pair = blockIdx.x>>5 handles chains 2*pair and 2*pair+1.
// Per chain per step: stage h (8x1024) -> 8x8 f32x2 tile over K-chunk of 16
// (kc = tid&63, p = tid>>6 warp-uniform) -> 64-way output-major reduction ->
// relu epilogue -> non-blocking barrier arrive. Chain B's compute hides
// chain A's barrier/L2 latency and vice versa.
// ---------------------------------------------------------------------------
__global__ void __launch_bounds__(TB, 1) rnn_recur(
    const float* __restrict__ hid_in,
    const float* __restrict__ Whh,
    float* __restrict__ out)
{
    extern __shared__ float sm[];
    float* wsm = sm;                  // 32 rows x HRow = 34816 floats (136 KB)
    float* R   = sm + 32 * HRow;      // union: h stage (8x1088) / red (256x66)

    const int tid  = threadIdx.x;
    const int pair = blockIdx.x >> 5;       // 0..3
    const int cg   = blockIdx.x & 31;       // 0..31
    const int c0   = cg * 32;
    const int ch0  = pair * 2;              // first chain id

    const int kc = tid & 63;                // K-chunk of 16 floats
    const int p  = tid >> 6;                // warp-uniform col-octet 0..3
    const int kco = (kc >> 1) * CH + (kc & 1) * 16;

    // ---- stage W_hh slice once: rows c0..c0+31 ----
    const float2* W2 = (const float2*)Whh;
    #pragma unroll 4
    for (int i = tid; i < 32 * 512; i += TB) {
        int r = i >> 9, q = i & 511;
        *(float2*)&wsm[r * HRow + (q >> 4) * CH + (q & 15) * 2] =
            __ldg(&W2[(c0 + r) * 512 + q]);
    }

    const float* hb_ = R + kco;
    const float* wb_ = wsm + p * 8 * HRow + kco;

    float* hid_out = out + HID_OFF;
    float* hlast   = out + HL_OFF;

    // epilogue: thread owns one output per chain: b = tid>>5, c = tid&31
    const int eb = tid >> 5;
    const int gc = c0 + (tid & 31);

    unsigned gen0[2];
    if (tid == 0) {
        gen0[0] = *(volatile unsigned*)&g_gen2[(ch0    ) * 32];
        gen0[1] = *(volatile unsigned*)&g_gen2[(ch0 + 1) * 32];
    }

    #pragma unroll 1
    for (int s = 0; s < T_; ++s) {
        #pragma unroll 1
        for (int ch = 0; ch < 2; ++ch) {
            const int chain = ch0 + ch;
            const int bb0   = chain * 8;
            const int gb    = bb0 + eb;

            // prefetch xw for this thread's output (own location, safe early)
            float xw = __ldcg(&hid_out[((size_t)gb * T_ + s) * H_ + gc]);

            // ---- wait for previous step of this chain (usually free) ----
            if (s > 0) {
                if (tid == 0) {
                    volatile unsigned* gp = &g_gen2[chain * 32];
                    unsigned tgt = gen0[ch] + (unsigned)s;
                    while ((int)(*gp - tgt) < 0) { }
                }
                __syncthreads();
            }

            // ---- stage h slice (8 x 1024) ----
            const float2* hsrc = (s == 0) ? (const float2*)hid_in
                                          : (const float2*)g_hbuf[(s - 1) & 1];
            #pragma unroll
            for (int i = tid; i < 8 * 512; i += TB) {
                int r = i >> 9, q = i & 511;
                *(float2*)&R[r * HRow + (q >> 4) * CH + (q & 15) * 2] =
                    __ldcg(&hsrc[(bb0 + r) * 512 + q]);
            }
            __syncthreads();

            // ---- 8x8 tile over private K-chunk of 16 ----
            ull acc[64];
            #pragma unroll
            for (int i = 0; i < 64; ++i) acc[i] = 0ull;

            #pragma unroll
            for (int k2 = 0; k2 < 8; ++k2) {
                ull hv[8];
                #pragma unroll
                for (int i = 0; i < 8; ++i)
                    hv[i] = *(const ull*)(hb_ + i * HRow + k2 * 2);
                ull wv[4];
                #pragma unroll
                for (int j = 0; j < 4; ++j)
                    wv[j] = *(const ull*)(wb_ + j * HRow + k2 * 2);
                #pragma unroll
                for (int i = 0; i < 8; ++i)
                    #pragma unroll
                    for (int j = 0; j < 4; ++j)
                        acc[i * 8 + j] = f2fma(hv[i], wv[j], acc[i * 8 + j]);
                #pragma unroll
                for (int j = 0; j < 4; ++j)
                    wv[j] = *(const ull*)(wb_ + (j + 4) * HRow + k2 * 2);
                #pragma unroll
                for (int i = 0; i < 8; ++i)
                    #pragma unroll
                    for (int j = 0; j < 4; ++j)
                        acc[i * 8 + j + 4] = f2fma(hv[i], wv[j], acc[i * 8 + j + 4]);
            }
            __syncthreads();   // h reads done before red overwrites R

            // ---- partials, output-major: R[o*RST + kc] ----
            #pragma unroll
            for (int i = 0; i < 8; ++i)
                #pragma unroll
                for (int j = 0; j < 8; ++j) {
                    int o = i * 32 + p * 8 + j;
                    R[o * RST + kc] = pairsum(acc[i * 8 + j]);
                }
            __syncthreads();

            // ---- 64-way reduction: thread sums output o = tid ----
            ull a = 0;
            #pragma unroll
            for (int r2 = 0; r2 < 32; ++r2)
                a = f2add(a, *(const ull*)&R[tid * RST + 2 * r2]);
            float v = pairsum(a);

            float rr = fmaxf(xw + v, 0.0f);
            hid_out[((size_t)gb * T_ + s) * H_ + gc] = rr;
            g_hbuf[s & 1][gb * H_ + gc] = rr;
            if (s == T_ - 1) hlast[gb * H_ + gc] = rr;

            // ---- publish + non-blocking arrive ----
            __threadfence();
            __syncthreads();
            if (s != T_ - 1 && tid == 0) {
                if (atomicAdd(&g_cnt[chain * 32], 1) == 31) {
                    g_cnt[chain * 32] = 0;
                    __threadfence();
                    atomicAdd((unsigned*)&g_gen2[chain * 32], 1);
                }
            }
        }
    }
}

// ---------------------------------------------------------------------------
// Kernel C: output_list[bt][o] = hid[bt]·W_out[o] + b_out[o]   (f32x2)
// ---------------------------------------------------------------------------
__global__ void __launch_bounds__(256) out_kernel(
    const float* __restrict__ hid, const float* __restrict__ Wout,
    const float* __restrict__ bout, float* __restrict__ outp)
{
    __shared__ float hs[128 * CH];
    __shared__ float ws2[64 * CH];

    const int tid = threadIdx.x;
    const int btb = blockIdx.x * 128;
    const int tx = tid & 15, ty = tid >> 4;

    const float2* hid2  = (const float2*)hid;
    const float2* wout2 = (const float2*)Wout;

    ull acc[8][4];
    #pragma unroll
    for (int i = 0; i < 8; ++i)
        #pragma unroll
        for (int j = 0; j < 4; ++j) acc[i][j] = 0ull;

    for (int kcb = 0; kcb < 512; kcb += 16) {
        #pragma unroll
        for (int i = tid; i < 128 * 16; i += 256) {
            int r = i >> 4, q = i & 15;
            *(float2*)&hs[r * CH + q * 2] = hid2[(btb + r) * 512 + kcb + q];
        }
        #pragma unroll
        for (int i = tid; i < 64 * 16; i += 256) {
            int r = i >> 4, q = i & 15;
            *(float2*)&ws2[r * CH + q * 2] = wout2[r * 512 + kcb + q];
        }
        __syncthreads();

        #pragma unroll
        for (int k2 = 0; k2 < 16; ++k2) {
            ull a[8], b[4];
            #pragma unroll
            for (int i = 0; i < 8; ++i)
                a[i] = *(const ull*)&hs[(ty + 16 * i) * CH + k2 * 2];
            #pragma unroll
            for (int j = 0; j < 4; ++j)
                b[j] = *(const ull*)&ws2[(tx + 16 * j) * CH + k2 * 2];
            #pragma unroll
            for (int i = 0; i < 8; ++i)
                #pragma unroll
                for (int j = 0; j < 4; ++j)
                    acc[i][j] = f2fma(a[i], b[j], acc[i][j]);
        }
        __syncthreads();
    }

    #pragma unroll
    for (int j = 0; j < 4; ++j) {
        int o = tx + 16 * j;
        float bb = bout[o];
        #pragma unroll
        for (int i = 0; i < 8; ++i)
            outp[(btb + ty + 16 * i) * O_ + o] = pairsum(acc[i][j]) + bb;
    }
}

// ---------------------------------------------------------------------------
extern "C" void kernel_launch(void* const* d_in, const int* in_sizes, int n_in,
                              void* d_out, int out_size) {
    const float* x      = (const float*)d_in[0];
    const float* hidden = (const float*)d_in[1];
    const float* W_ih   = (const float*)d_in[2];
    const float* W_hh   = (const float*)d_in[3];
    const float* b_ih   = (const float*)d_in[4];
    const float* b_hh   = (const float*)d_in[5];
    const float* W_out  = (const float*)d_in[6];
    const float* b_out  = (const float*)d_in[7];
    float* out = (float*)d_out;

    dim3 gA(H_ / 64, (B_ * T_) / 64);
    xw_kernel<<<gA, 256>>>(x, W_ih, b_ih, b_hh, out + HID_OFF);

    // SMEM: W (32*1088) + union region (256*66) = 51712 floats = 206848 B
    size_t smemB = (size_t)(32 * HRow + 256 * RST) * sizeof(float);
    cudaFuncSetAttribute(rnn_recur, cudaFuncAttributeMaxDynamicSharedMemorySize,
                         (int)smemB);
    rnn_recur<<<NBLK, TB, smemB>>>(hidden, W_hh, out);

    out_kernel<<<(B_ * T_) / 128, 256>>>(out + HID_OFF, W_out, b_out, out + OUT_OFF);
}

// round 5
// speedup vs baseline: 1.5601x; 1.5601x over previous
#include <cuda_runtime.h>

// ---------------------------------------------------------------------------
// Elman RNN (relu), B=64, T=512, I=64, H=1024, O=64
// out = [ hidden_list (B,T,H) | output_list (B,T,O) | h_last (1,B,H) ]
// ---------------------------------------------------------------------------

#define B_   64
#define T_   512
#define I_   64
#define H_   1024
#define O_   64

#define HID_OFF  0
#define OUT_OFF  (B_ * T_ * H_)              // 33554432
#define HL_OFF   (OUT_OFF + B_ * T_ * O_)    // 35651584

#define NBLK 128        // persistent blocks (1/SM)
#define TB   256        // 2 warps / SMSP

// SMEM layout (floats): 32 K-chunks of 32 floats, each padded to 34
#define CH    34
#define HRow  1088      // 32 * 34

// scratch: h double buffer + per-batch-group barrier state
__device__ float    g_hbuf[2][B_ * H_];
__device__ unsigned g_cnt[4 * 32];
__device__ unsigned g_gen2[4 * 32];

typedef unsigned long long ull;

__device__ __forceinline__ ull f2fma(ull a, ull b, ull c) {
    ull d;
    asm("fma.rn.f32x2 %0, %1, %2, %3;" : "=l"(d) : "l"(a), "l"(b), "l"(c));
    return d;
}
__device__ __forceinline__ float pairsum(ull a) {
    float lo = __uint_as_float((unsigned)(a & 0xffffffffull));
    float hi = __uint_as_float((unsigned)(a >> 32));
    return lo + hi;
}
__device__ __forceinline__ unsigned ld_acq(unsigned* p) {
    unsigned v;
    asm volatile("ld.acquire.gpu.u32 %0, [%1];" : "=r"(v) : "l"(p) : "memory");
    return v;
}
__device__ __forceinline__ unsigned atom_add_rel(unsigned* p, unsigned v) {
    unsigned o;
    asm volatile("atom.add.release.gpu.u32 %0, [%1], %2;"
                 : "=r"(o) : "l"(p), "r"(v) : "memory");
    return o;
}

// ---------------------------------------------------------------------------
// Kernel A: xw[bt][h] = x[bt]·W_ih[h] + b_ih[h] + b_hh[h]  -> hidden region
// ---------------------------------------------------------------------------
__global__ void __launch_bounds__(256) xw_kernel(
    const float* __restrict__ x, const float* __restrict__ Wih,
    const float* __restrict__ bih, const float* __restrict__ bhh,
    float* __restrict__ hid_out)
{
    __shared__ float xs[64 * 65];
    __shared__ float ws[64 * 65];

    const int tid = threadIdx.x;
    const int hb  = blockIdx.x * 64;
    const int btb = blockIdx.y * 64;

    #pragma unroll
    for (int i = tid; i < 64 * 64; i += 256) {
        int r = i >> 6, c = i & 63;
        xs[r * 65 + c] = x[(btb + r) * 64 + c];
        ws[r * 65 + c] = Wih[(hb + r) * 64 + c];
    }
    __syncthreads();

    const int tx = tid & 15, ty = tid >> 4;
    float acc[4][4] = {};

    #pragma unroll 8
    for (int k = 0; k < 64; ++k) {
        float a0 = xs[(ty     ) * 65 + k];
        float a1 = xs[(ty + 16) * 65 + k];
        float a2 = xs[(ty + 32) * 65 + k];
        float a3 = xs[(ty + 48) * 65 + k];
        float b0 = ws[(tx     ) * 65 + k];
        float b1 = ws[(tx + 16) * 65 + k];
        float b2 = ws[(tx + 32) * 65 + k];
        float b3 = ws[(tx + 48) * 65 + k];
        acc[0][0] += a0 * b0; acc[0][1] += a0 * b1; acc[0][2] += a0 * b2; acc[0][3] += a0 * b3;
        acc[1][0] += a1 * b0; acc[1][1] += a1 * b1; acc[1][2] += a1 * b2; acc[1][3] += a1 * b3;
        acc[2][0] += a2 * b0; acc[2][1] += a2 * b1; acc[2][2] += a2 * b2; acc[2][3] += a2 * b3;
        acc[3][0] += a3 * b0; acc[3][1] += a3 * b1; acc[3][2] += a3 * b2; acc[3][3] += a3 * b3;
    }

    #pragma unroll
    for (int j = 0; j < 4; ++j) {
        int h = hb + tx + 16 * j;
        float bb = bih[h] + bhh[h];
        #pragma unroll
        for (int i = 0; i < 4; ++i) {
            int bt = btb + ty + 16 * i;
            hid_out[bt * H_ + h] = acc[i][j] + bb;
        }
    }
}

// ---------------------------------------------------------------------------
// Kernel B: persistent recurrence (R3 structure + shuffle reduction).
// 128 blocks = 4 batch-groups(16 batches) x 32 col-groups(32 cols).
// kc = tid&31 (lane, K-chunk of 32), p = tid>>5 (warp-uniform tile position:
// pm batch octet, pn col octet). Each thread: 8x8 f32x2 tile over its
// K-chunk; then pairsum + 5-round butterfly shuffle reduction inside the
// warp -> lane ends with outputs (batch pm*8+(lane>>2), cols pn*8+2*(lane&3)
// .. +1) -> float2 relu epilogue -> release/acquire grid barrier.
// ---------------------------------------------------------------------------
__global__ void __launch_bounds__(TB, 1) rnn_recur(
    const float* __restrict__ hid_in,
    const float* __restrict__ Whh,
    float* __restrict__ out)
{
    extern __shared__ float sm[];
    float* wsm = sm;                 // 32 rows x HRow  (~136 KB)
    float* hsm = sm + 32 * HRow;     // 16 rows x HRow  (~68 KB)

    const int tid = threadIdx.x;
    const int bi  = blockIdx.x >> 5;
    const int ci  = blockIdx.x & 31;
    const int b0  = bi * 16;
    const int c0  = ci * 32;

    const int lane = tid & 31;
    const int kc   = lane;             // K-chunk (lane-spanning)
    const int p    = tid >> 5;         // warp-uniform tile position 0..7
    const int pm   = p & 1;
    const int pn   = p >> 1;

    // ---- stage W_hh slice once: rows c0..c0+31, chunked layout ----
    const float2* W2 = (const float2*)Whh;
    #pragma unroll 4
    for (int i = tid; i < 32 * 512; i += TB) {
        int r = i >> 9, q = i & 511;
        *(float2*)&wsm[r * HRow + (q >> 4) * CH + (q & 15) * 2] =
            __ldg(&W2[(c0 + r) * 512 + q]);
    }

    const float* hb_ = hsm + pm * 8 * HRow + kc * CH;
    const float* wb_ = wsm + pn * 8 * HRow + kc * CH;

    float* hid_out = out + HID_OFF;
    float* hlast   = out + HL_OFF;

    // epilogue mapping (post-shuffle): lane holds outputs 2*lane, 2*lane+1 of
    // the warp's 64 = (batch pm*8 + (lane>>2), cols pn*8 + 2*(lane&3) + {0,1})
    const int gb = b0 + pm * 8 + (lane >> 2);
    const int gc = c0 + pn * 8 + 2 * (lane & 3);

    unsigned gen0 = 0;
    if (tid == 0) gen0 = ld_acq(&g_gen2[bi * 32]);

    #pragma unroll 1
    for (int s = 0; s < T_; ++s) {
        // prefetch xw for this thread's two outputs (own location, safe early)
        float2 xw = *(const float2*)&hid_out[((size_t)gb * T_ + s) * H_ + gc];

        // ---- wait for previous step (release/acquire) ----
        if (s > 0) {
            if (tid == 0) {
                unsigned tgt = gen0 + (unsigned)s;
                while ((int)(ld_acq(&g_gen2[bi * 32]) - tgt) < 0) { }
            }
            __syncthreads();   // also separates prev FMA reads from restaging
        }

        // ---- stage h slice (16 x 1024) into chunked SMEM layout ----
        const float2* hsrc = (s == 0) ? (const float2*)hid_in
                                      : (const float2*)g_hbuf[(s - 1) & 1];
        #pragma unroll 8
        for (int i = tid; i < 16 * 512; i += TB) {
            int r = i >> 9, q = i & 511;
            *(float2*)&hsm[r * HRow + (q >> 4) * CH + (q & 15) * 2] =
                __ldcg(&hsrc[(b0 + r) * 512 + q]);
        }
        __syncthreads();

        // ---- 8x8 tile over private K-chunk of 32 ----
        ull acc[64];
        #pragma unroll
        for (int i = 0; i < 64; ++i) acc[i] = 0ull;

        #pragma unroll
        for (int k2 = 0; k2 < 16; ++k2) {
            ull hv[8];
            #pragma unroll
            for (int i = 0; i < 8; ++i)
                hv[i] = *(const ull*)(hb_ + i * HRow + k2 * 2);
            ull wv[4];
            #pragma unroll
            for (int j = 0; j < 4; ++j)
                wv[j] = *(const ull*)(wb_ + j * HRow + k2 * 2);
            #pragma unroll
            for (int i = 0; i < 8; ++i)
                #pragma unroll
                for (int j = 0; j < 4; ++j)
                    acc[i * 8 + j] = f2fma(hv[i], wv[j], acc[i * 8 + j]);
            #pragma unroll
            for (int j = 0; j < 4; ++j)
                wv[j] = *(const ull*)(wb_ + (j + 4) * HRow + k2 * 2);
            #pragma unroll
            for (int i = 0; i < 8; ++i)
                #pragma unroll
                for (int j = 0; j < 4; ++j)
                    acc[i * 8 + j + 4] = f2fma(hv[i], wv[j], acc[i * 8 + j + 4]);
        }

        // ---- pairsum then 5-round butterfly shuffle reduction ----
        float vals[64];
        #pragma unroll
        for (int v = 0; v < 64; ++v) vals[v] = pairsum(acc[v]);

        #pragma unroll
        for (int m = 16, cnt = 32; m >= 1; m >>= 1, cnt >>= 1) {
            bool up = (lane & m) != 0;
            #pragma unroll
            for (int i = 0; i < 32; ++i) {      // only i < cnt active
                if (i >= cnt) break;
                float send = up ? vals[i] : vals[i + cnt];
                float keep = up ? vals[i + cnt] : vals[i];
                float recv = __shfl_xor_sync(0xffffffffu, send, m);
                vals[i] = keep + recv;
            }
        }
        // lane now holds vals[0], vals[1] = outputs 2*lane, 2*lane+1

        float2 rr;
        rr.x = fmaxf(xw.x + vals[0], 0.0f);
        rr.y = fmaxf(xw.y + vals[1], 0.0f);

        *(float2*)&hid_out[((size_t)gb * T_ + s) * H_ + gc] = rr;
        *(float2*)&g_hbuf[s & 1][gb * H_ + gc] = rr;
        if (s == T_ - 1)
            *(float2*)&hlast[gb * H_ + gc] = rr;

        // ---- barrier arrive (release), skip after last step ----
        if (s != T_ - 1) {
            __syncthreads();          // all epilogue stores issued
            if (tid == 0) {
                if (atom_add_rel(&g_cnt[bi * 32], 1) == 31) {
                    g_cnt[bi * 32] = 0;                       // plain store
                    atom_add_rel(&g_gen2[bi * 32], 1);        // orders reset
                }
            }
        }
    }
}

// ---------------------------------------------------------------------------
// Kernel C: output_list[bt][o] = hid[bt]·W_out[o] + b_out[o]   (f32x2)
// ---------------------------------------------------------------------------
__global__ void __launch_bounds__(256) out_kernel(
    const float* __restrict__ hid, const float* __restrict__ Wout,
    const float* __restrict__ bout, float* __restrict__ outp)
{
    __shared__ float hs[128 * CH];
    __shared__ float ws2[64 * CH];

    const int tid = threadIdx.x;
    const int btb = blockIdx.x * 128;
    const int tx = tid & 15, ty = tid >> 4;

    const float2* hid2  = (const float2*)hid;
    const float2* wout2 = (const float2*)Wout;

    ull acc[8][4];
    #pragma unroll
    for (int i = 0; i < 8; ++i)
        #pragma unroll
        for (int j = 0; j < 4; ++j) acc[i][j] = 0ull;

    for (int kcb = 0; kcb < 512; kcb += 16) {
        #pragma unroll
        for (int i = tid; i < 128 * 16; i += 256) {
            int r = i >> 4, q = i & 15;
            *(float2*)&hs[r * CH + q * 2] = hid2[(btb + r) * 512 + kcb + q];
        }
        #pragma unroll
        for (int i = tid; i < 64 * 16; i += 256) {
            int r = i >> 4, q = i & 15;
            *(float2*)&ws2[r * CH + q * 2] = wout2[r * 512 + kcb + q];
        }
        __syncthreads();

        #pragma unroll
        for (int k2 = 0; k2 < 16; ++k2) {
            ull a[8], b[4];
            #pragma unroll
            for (int i = 0; i < 8; ++i)
                a[i] = *(const ull*)&hs[(ty + 16 * i) * CH + k2 * 2];
            #pragma unroll
            for (int j = 0; j < 4; ++j)
                b[j] = *(const ull*)&ws2[(tx + 16 * j) * CH + k2 * 2];
            #pragma unroll
            for (int i = 0; i < 8; ++i)
                #pragma unroll
                for (int j = 0; j < 4; ++j)
                    acc[i][j] = f2fma(a[i], b[j], acc[i][j]);
        }
        __syncthreads();
    }

    #pragma unroll
    for (int j = 0; j < 4; ++j) {
        int o = tx + 16 * j;
        float bb = bout[o];
        #pragma unroll
        for (int i = 0; i < 8; ++i)
            outp[(btb + ty + 16 * i) * O_ + o] = pairsum(acc[i][j]) + bb;
    }
}

// ---------------------------------------------------------------------------
extern "C" void kernel_launch(void* const* d_in, const int* in_sizes, int n_in,
                              void* d_out, int out_size) {
    const float* x      = (const float*)d_in[0];
    const float* hidden = (const float*)d_in[1];
    const float* W_ih   = (const float*)d_in[2];
    const float* W_hh   = (const float*)d_in[3];
    const float* b_ih   = (const float*)d_in[4];
    const float* b_hh   = (const float*)d_in[5];
    const float* W_out  = (const float*)d_in[6];
    const float* b_out  = (const float*)d_in[7];
    float* out = (float*)d_out;

    dim3 gA(H_ / 64, (B_ * T_) / 64);
    xw_kernel<<<gA, 256>>>(x, W_ih, b_ih, b_hh, out + HID_OFF);

    size_t smemB = (size_t)(48 * HRow) * sizeof(float);   // 208,896 B
    cudaFuncSetAttribute(rnn_recur, cudaFuncAttributeMaxDynamicSharedMemorySize,
                         (int)smemB);
    rnn_recur<<<NBLK, TB, smemB>>>(hidden, W_hh, out);

    out_kernel<<<(B_ * T_) / 128, 256>>>(out + HID_OFF, W_out, b_out, out + OUT_OFF);
}